// round 1
// baseline (speedup 1.0000x reference)
#include <cuda_runtime.h>
#include <cuda_bf16.h>
#include <cstdint>

#define NPROMPT 50
#define PPAD 64
#define D 768
#define KC 64
#define NKIT (D / KC)          // 12
#define NTILE 256              // pe vectors per CTA
#define LDA (D + 8)            // 776 halves, conflict-free ldmatrix
#define LDB (KC + 8)           // 72 halves
#define NVEC 201728            // 1024 * 197
#define NBLK (NVEC / NTILE)    // 788 exactly
#define EPSV 1e-6f

__device__ __align__(16) __nv_bfloat16 g_A[PPAD * D];
__device__ float g_ns[PPAD];
__device__ double g_acc;

// ---------------------------------------------------------------- prep ----
__global__ void prep_kernel(const float* __restrict__ src) {
    int p = blockIdx.x, tid = threadIdx.x;
    float local = 0.f;
    for (int k = tid; k < D; k += blockDim.x) {
        float v = (p < NPROMPT) ? src[p * D + k] + EPSV : 0.f;
        g_A[p * D + k] = __float2bfloat16(v);
        local += v * v;
    }
    __shared__ float sh[256];
    sh[tid] = local;
    __syncthreads();
    for (int s = 128; s > 0; s >>= 1) {
        if (tid < s) sh[tid] += sh[tid + s];
        __syncthreads();
    }
    if (tid == 0) {
        g_ns[p] = sh[0];
        if (p == 0) g_acc = 0.0;
    }
}

// ------------------------------------------------------------- helpers ----
__device__ __forceinline__ void ldsm4(uint32_t& r0, uint32_t& r1, uint32_t& r2,
                                      uint32_t& r3, uint32_t addr) {
    asm volatile("ldmatrix.sync.aligned.m8n8.x4.shared.b16 {%0,%1,%2,%3}, [%4];\n"
                 : "=r"(r0), "=r"(r1), "=r"(r2), "=r"(r3)
                 : "r"(addr));
}

__device__ __forceinline__ void mma16816(float* c, uint32_t a0, uint32_t a1,
                                         uint32_t a2, uint32_t a3, uint32_t b0,
                                         uint32_t b1) {
    asm volatile(
        "mma.sync.aligned.m16n8k16.row.col.f32.bf16.bf16.f32 "
        "{%0,%1,%2,%3}, {%4,%5,%6,%7}, {%8,%9}, {%0,%1,%2,%3};\n"
        : "+f"(c[0]), "+f"(c[1]), "+f"(c[2]), "+f"(c[3])
        : "r"(a0), "r"(a1), "r"(a2), "r"(a3), "r"(b0), "r"(b1));
}

// ---------------------------------------------------------------- main ----
// smem: A tile (64 x 776 bf16) + double-buffered B (2 x 256 x 72 bf16)
//       + npe[256] f32 + ns[64] f32 + red[8] f32
constexpr int SMEM_BYTES =
    (PPAD * LDA + 2 * NTILE * LDB) * 2 + (NTILE + PPAD + 8) * 4;

__global__ void __launch_bounds__(256, 1)
dist_kernel(const float* __restrict__ pe) {
    extern __shared__ char smem_raw[];
    __nv_bfloat16* sA = (__nv_bfloat16*)smem_raw;
    __nv_bfloat16* sB = sA + PPAD * LDA;
    float* sNpe = (float*)(sB + 2 * NTILE * LDB);
    float* sNs = sNpe + NTILE;
    float* sRed = sNs + PPAD;

    const int tid = threadIdx.x;
    const int warp = tid >> 5, lane = tid & 31;
    const int m_base = (warp >> 1) * 16;   // 4 warps over M=64
    const int n_base = (warp & 1) * 128;   // 2 warps over N=256

    // Copy prompt tile (bf16) into padded smem
    {
        const uint2* src = (const uint2*)g_A;
        for (int c = tid; c < PPAD * D / 4; c += 256) {
            int r = c / (D / 4), cc = c % (D / 4);
            *(uint2*)(sA + r * LDA + cc * 4) = src[c];
        }
    }
    if (tid < PPAD) sNs[tid] = g_ns[tid];
    sNpe[tid] = 0.f;

    const float* peBase = pe + (size_t)blockIdx.x * NTILE * D;
    const int rowT = tid >> 4;        // 0..15
    const int colT = (tid & 15) * 4;  // float offset within 64-chunk

    // Preload chunk 0 into buffer 0 (fp32 LDG -> bf16 STS, accumulate |pe|^2)
    {
        float4 v[4];
#pragma unroll
        for (int g = 0; g < 4; ++g) {
#pragma unroll
            for (int j = 0; j < 4; ++j) {
                int row = (g * 4 + j) * 16 + rowT;
                v[j] = *(const float4*)(peBase + (size_t)row * D + colT);
            }
#pragma unroll
            for (int j = 0; j < 4; ++j) {
                int row = (g * 4 + j) * 16 + rowT;
                __nv_bfloat162* dst = (__nv_bfloat162*)(sB + row * LDB + colT);
                dst[0] = __floats2bfloat162_rn(v[j].x, v[j].y);
                dst[1] = __floats2bfloat162_rn(v[j].z, v[j].w);
                atomicAdd(&sNpe[row], v[j].x * v[j].x + v[j].y * v[j].y +
                                          v[j].z * v[j].z + v[j].w * v[j].w);
            }
        }
    }

    float acc[16][4];
#pragma unroll
    for (int j = 0; j < 16; ++j)
#pragma unroll
        for (int q = 0; q < 4; ++q) acc[j][q] = 0.f;

    __syncthreads();

    const uint32_t sA_u = (uint32_t)__cvta_generic_to_shared(sA);
    const uint32_t sB_u = (uint32_t)__cvta_generic_to_shared(sB);
    const uint32_t a_off =
        ((uint32_t)((m_base + (lane & 15)) * LDA + (lane >> 4) * 8)) * 2;
    const uint32_t b_row = (uint32_t)(n_base + ((lane >> 4) & 1) * 8 + (lane & 7));
    const uint32_t b_k = ((lane >> 3) & 1) * 8;

#define LDGG(g, vv)                                                           \
    {                                                                         \
        _Pragma("unroll") for (int j = 0; j < 4; ++j) {                       \
            int row = ((g)*4 + j) * 16 + rowT;                                \
            vv[j] = *(const float4*)(peBase + (size_t)row * D + kn + colT);   \
        }                                                                     \
    }
#define STSG(g, vv)                                                           \
    {                                                                         \
        _Pragma("unroll") for (int j = 0; j < 4; ++j) {                       \
            int row = ((g)*4 + j) * 16 + rowT;                                \
            __nv_bfloat162* dst = (__nv_bfloat162*)(bufN + row * LDB + colT); \
            dst[0] = __floats2bfloat162_rn(vv[j].x, vv[j].y);                 \
            dst[1] = __floats2bfloat162_rn(vv[j].z, vv[j].w);                 \
            atomicAdd(&sNpe[row], vv[j].x * vv[j].x + vv[j].y * vv[j].y +     \
                                      vv[j].z * vv[j].z + vv[j].w * vv[j].w); \
        }                                                                     \
    }
#define STEP(s)                                                               \
    {                                                                         \
        uint32_t a0, a1, a2, a3;                                              \
        ldsm4(a0, a1, a2, a3, sA_u + a_off + (s)*16 * 2);                     \
        _Pragma("unroll") for (int jj = 0; jj < 8; ++jj) {                    \
            uint32_t b0, b1, b2, b3;                                          \
            uint32_t baddr =                                                  \
                sbc + ((b_row + jj * 16) * LDB + (s)*16 + b_k) * 2;           \
            ldsm4(b0, b1, b2, b3, baddr);                                     \
            mma16816(acc[2 * jj], a0, a1, a2, a3, b0, b1);                    \
            mma16816(acc[2 * jj + 1], a0, a1, a2, a3, b2, b3);                \
        }                                                                     \
    }

    for (int it = 0; it < NKIT; ++it) {
        const uint32_t sbc = sB_u + (uint32_t)((it & 1) * (NTILE * LDB * 2));
        __nv_bfloat16* bufN = sB + ((it + 1) & 1) * (NTILE * LDB);
        const bool dl = (it + 1) < NKIT;
        const int kn = (it + 1) * KC;
        float4 v0[4], v1[4], v2[4], v3[4];

        if (dl) LDGG(0, v0);
        STEP(0);
        if (dl) { STSG(0, v0); LDGG(1, v1); }
        STEP(1);
        if (dl) { STSG(1, v1); LDGG(2, v2); }
        STEP(2);
        if (dl) { STSG(2, v2); LDGG(3, v3); }
        STEP(3);
        if (dl) { STSG(3, v3); }
        __syncthreads();
    }

    // Epilogue: d = sqrt(|s'|^2 + |pe|^2 - 2*dot), masked to real prompts
    float lsum = 0.f;
    const int r = lane >> 2, c2 = (lane & 3) * 2;
#pragma unroll
    for (int j = 0; j < 16; ++j) {
        int n = n_base + j * 8 + c2;
        float np0 = sNpe[n], np1 = sNpe[n + 1];
        int m0 = m_base + r;
        if (m0 < NPROMPT) {
            float ns0 = sNs[m0];
            lsum += sqrtf(fmaxf(ns0 + np0 - 2.f * acc[j][0], 0.f));
            lsum += sqrtf(fmaxf(ns0 + np1 - 2.f * acc[j][1], 0.f));
        }
        int m1 = m0 + 8;
        if (m1 < NPROMPT) {
            float ns1 = sNs[m1];
            lsum += sqrtf(fmaxf(ns1 + np0 - 2.f * acc[j][2], 0.f));
            lsum += sqrtf(fmaxf(ns1 + np1 - 2.f * acc[j][3], 0.f));
        }
    }
#pragma unroll
    for (int o = 16; o > 0; o >>= 1)
        lsum += __shfl_xor_sync(0xffffffffu, lsum, o);
    if (lane == 0) sRed[warp] = lsum;
    __syncthreads();
    if (warp == 0) {
        float s = (lane < 8) ? sRed[lane] : 0.f;
#pragma unroll
        for (int o = 4; o > 0; o >>= 1)
            s += __shfl_xor_sync(0xffffffffu, s, o);
        if (lane == 0) atomicAdd(&g_acc, (double)s);
    }
}

// -------------------------------------------------------------- finish ----
__global__ void finish_kernel(float* out) {
    out[0] = (float)(g_acc * (1.0 / ((double)NPROMPT * 197.0 * 1024.0)));
}

// -------------------------------------------------------------- launch ----
extern "C" void kernel_launch(void* const* d_in, const int* in_sizes, int n_in,
                              void* d_out, int out_size) {
    const float* src = (const float*)d_in[0];  // source_prompt [50,768]
    const float* pe = (const float*)d_in[1];   // patch_embeds [1024,197,768]
    float* out = (float*)d_out;

    cudaFuncSetAttribute(dist_kernel, cudaFuncAttributeMaxDynamicSharedMemorySize,
                         SMEM_BYTES);

    prep_kernel<<<PPAD, 256>>>(src);
    dist_kernel<<<NBLK, 256, SMEM_BYTES>>>(pe);
    finish_kernel<<<1, 1>>>(out);
}

// round 4
// speedup vs baseline: 3.5436x; 3.5436x over previous
#include <cuda_runtime.h>
#include <cuda_bf16.h>
#include <cstdint>

#define NPROMPT 50
#define MPAD 64              // padded prompt count (GEMM M)
#define D 768
#define KC 64                // k per chunk
#define NCHUNK (D / KC)      // 12
#define NTILE 128            // pe rows per CTA (GEMM N)
#define NVEC 201728          // 1024 * 197
#define NBLK (NVEC / NTILE)  // 1576 exactly
#define EPSV 1e-6f

#define LDA 776              // prompt smem row stride (halves), 1552B: 97*16B -> conflict-free
#define LDB 72               // pe smem row stride (halves), 144B: 9*16B -> conflict-free

__device__ __align__(16) __nv_bfloat16 g_B[MPAD * D];
__device__ float g_ns[MPAD];
__device__ double g_acc;

// ---------------------------------------------------------------- prep ----
__global__ void prep_kernel(const float* __restrict__ src) {
    int p = blockIdx.x, tid = threadIdx.x;
    float local = 0.f;
    for (int k = tid; k < D; k += blockDim.x) {
        float v = (p < NPROMPT) ? src[p * D + k] + EPSV : 0.f;
        g_B[p * D + k] = __float2bfloat16(v);
        local += v * v;
    }
    __shared__ float sh[256];
    sh[tid] = local;
    __syncthreads();
    for (int s = 128; s > 0; s >>= 1) {
        if (tid < s) sh[tid] += sh[tid + s];
        __syncthreads();
    }
    if (tid == 0) {
        g_ns[p] = sh[0];
        if (p == 0) g_acc = 0.0;
    }
}

// ------------------------------------------------------------- helpers ----
__device__ __forceinline__ uint32_t pack_bf2(float lo, float hi) {
    __nv_bfloat162 t = __floats2bfloat162_rn(lo, hi);
    return *reinterpret_cast<uint32_t*>(&t);
}

__device__ __forceinline__ void ldsm4(uint32_t& r0, uint32_t& r1, uint32_t& r2,
                                      uint32_t& r3, uint32_t addr) {
    asm volatile("ldmatrix.sync.aligned.m8n8.x4.shared.b16 {%0,%1,%2,%3}, [%4];\n"
                 : "=r"(r0), "=r"(r1), "=r"(r2), "=r"(r3)
                 : "r"(addr));
}

__device__ __forceinline__ void mma16816(float* c, uint32_t a0, uint32_t a1,
                                         uint32_t a2, uint32_t a3, uint32_t b0,
                                         uint32_t b1) {
    asm volatile(
        "mma.sync.aligned.m16n8k16.row.col.f32.bf16.bf16.f32 "
        "{%0,%1,%2,%3}, {%4,%5,%6,%7}, {%8,%9}, {%0,%1,%2,%3};\n"
        : "+f"(c[0]), "+f"(c[1]), "+f"(c[2]), "+f"(c[3])
        : "r"(a0), "r"(a1), "r"(a2), "r"(a3), "r"(b0), "r"(b1));
}

// ---------------------------------------------------------------- main ----
// smem: prompts A [64 x 776 halves] + pe B double-buffer [2 x 128 x 72 halves]
//       + sNpe[128] + sNs[64] + sRed[8]
constexpr int SA_HALVES = MPAD * LDA;                 // 49664
constexpr int SB_HALVES = 2 * NTILE * LDB;            // 18432
constexpr int SMEM_BYTES = (SA_HALVES + SB_HALVES) * 2 + (NTILE + MPAD + 8) * 4;

__global__ void __launch_bounds__(256, 1)
dist_kernel(const float* __restrict__ pe) {
    extern __shared__ char smem_raw[];
    __nv_bfloat16* sA = (__nv_bfloat16*)smem_raw;
    __nv_bfloat16* sB = sA + SA_HALVES;
    float* sNpe = (float*)(sB + SB_HALVES);
    float* sNs = sNpe + NTILE;
    float* sRed = sNs + MPAD;

    const int tid = threadIdx.x;
    const int warp = tid >> 5, lane = tid & 31;
    const int m_base = (warp >> 1) * 16;  // 4 warps over M=64 prompts
    const int n_base = (warp & 1) * 64;   // 2 warps over N=128 pe rows

    // Load prompt tile (bf16, prepped) into padded smem
    {
        const uint4* src = (const uint4*)g_B;
        for (int i = tid; i < MPAD * D / 8; i += 256) {
            int r = i / (D / 8), q = i % (D / 8);
            *(uint4*)(sA + r * LDA + q * 8) = src[i];
        }
    }
    if (tid < MPAD) sNs[tid] = g_ns[tid];

    // pe loader mapping: thread owns row r0 = tid>>1, 32-float half c0
    const float* peBase = pe + (size_t)blockIdx.x * NTILE * D;
    const int r0 = tid >> 1;
    const int c0 = (tid & 1) * 32;
    const float* rowPtr = peBase + (size_t)r0 * D + c0;
    float nacc = 0.f;

    float4 v[8];
#define LDGS(ck)                                                              \
    {                                                                         \
        const float* p = rowPtr + (ck)*KC;                                    \
        _Pragma("unroll") for (int j = 0; j < 8; ++j)                         \
            v[j] = *(const float4*)(p + j * 4);                               \
    }
#define STSN(buf)                                                             \
    {                                                                         \
        __nv_bfloat16* dst = sB + (buf)*NTILE * LDB + r0 * LDB + c0;          \
        _Pragma("unroll") for (int j = 0; j < 8; ++j) {                       \
            nacc += v[j].x * v[j].x + v[j].y * v[j].y + v[j].z * v[j].z +     \
                    v[j].w * v[j].w;                                          \
            uint2 u;                                                          \
            u.x = pack_bf2(v[j].x, v[j].y);                                   \
            u.y = pack_bf2(v[j].z, v[j].w);                                   \
            *(uint2*)(dst + j * 4) = u;                                       \
        }                                                                     \
    }

    // fragments / accumulators: warp tile M16 x N64 -> 8 n8 tiles
    float acc[8][4];
#pragma unroll
    for (int j = 0; j < 8; ++j)
#pragma unroll
        for (int q = 0; q < 4; ++q) acc[j][q] = 0.f;

    const uint32_t sA_u = (uint32_t)__cvta_generic_to_shared(sA);
    const uint32_t sB_u = (uint32_t)__cvta_generic_to_shared(sB);
    const uint32_t a_addr =
        sA_u + (uint32_t)((m_base + (lane & 15)) * LDA + (lane >> 4) * 8) * 2;
    const uint32_t b_row = (uint32_t)(n_base + ((lane >> 4) & 1) * 8 + (lane & 7));
    const uint32_t b_k = ((lane >> 3) & 1) * 8;

#define STEP(s, acol, bbase)                                                  \
    {                                                                         \
        uint32_t a0, a1, a2, a3;                                              \
        ldsm4(a0, a1, a2, a3, a_addr + ((acol) + (s)*16) * 2);                \
        _Pragma("unroll") for (int jj = 0; jj < 4; ++jj) {                    \
            uint32_t b0, b1, b2, b3;                                          \
            uint32_t baddr =                                                  \
                (bbase) + ((b_row + jj * 16) * LDB + (s)*16 + b_k) * 2;       \
            ldsm4(b0, b1, b2, b3, baddr);                                     \
            mma16816(acc[2 * jj], a0, a1, a2, a3, b0, b1);                    \
            mma16816(acc[2 * jj + 1], a0, a1, a2, a3, b2, b3);                \
        }                                                                     \
    }

    // chunk 0 load
    LDGS(0);
    STSN(0);
    __syncthreads();

    for (int it = 0; it < NCHUNK; ++it) {
        const uint32_t bbase = sB_u + (uint32_t)((it & 1) * NTILE * LDB * 2);
        const int acol = it * KC;
        const bool dl = (it + 1) < NCHUNK;

        if (dl) LDGS(it + 1);     // prefetch next chunk into regs
        STEP(0, acol, bbase);
        STEP(1, acol, bbase);
        STEP(2, acol, bbase);
        STEP(3, acol, bbase);
        if (dl) STSN((it + 1) & 1);  // convert + store next chunk
        __syncthreads();
    }

    // ---- |pe|^2 per row: combine the two half-row partials
    nacc += __shfl_xor_sync(0xffffffffu, nacc, 1);
    if ((tid & 1) == 0) sNpe[r0] = nacc;
    __syncthreads();

    // ---- epilogue: d = sqrt(|s'|^2 + |pe|^2 - 2 dot), mask prompts >= 50
    float lsum = 0.f;
    const int r = lane >> 2, c2 = (lane & 3) * 2;
#pragma unroll
    for (int j = 0; j < 8; ++j) {
        int n = n_base + j * 8 + c2;   // pe row index
        float np0 = sNpe[n], np1 = sNpe[n + 1];
        int m0 = m_base + r;           // prompt index
        if (m0 < NPROMPT) {
            float ns0 = sNs[m0];
            lsum += sqrtf(fmaxf(ns0 + np0 - 2.f * acc[j][0], 0.f));
            lsum += sqrtf(fmaxf(ns0 + np1 - 2.f * acc[j][1], 0.f));
        }
        int m1 = m0 + 8;
        if (m1 < NPROMPT) {
            float ns1 = sNs[m1];
            lsum += sqrtf(fmaxf(ns1 + np0 - 2.f * acc[j][2], 0.f));
            lsum += sqrtf(fmaxf(ns1 + np1 - 2.f * acc[j][3], 0.f));
        }
    }
#pragma unroll
    for (int o = 16; o > 0; o >>= 1)
        lsum += __shfl_xor_sync(0xffffffffu, lsum, o);
    if (lane == 0) sRed[warp] = lsum;
    __syncthreads();
    if (warp == 0) {
        float s = (lane < 8) ? sRed[lane] : 0.f;
#pragma unroll
        for (int o = 4; o > 0; o >>= 1)
            s += __shfl_xor_sync(0xffffffffu, s, o);
        if (lane == 0) atomicAdd(&g_acc, (double)s);
    }
}

// -------------------------------------------------------------- finish ----
__global__ void finish_kernel(float* out) {
    out[0] = (float)(g_acc * (1.0 / ((double)NPROMPT * 197.0 * 1024.0)));
}

// -------------------------------------------------------------- launch ----
extern "C" void kernel_launch(void* const* d_in, const int* in_sizes, int n_in,
                              void* d_out, int out_size) {
    const float* src = (const float*)d_in[0];  // source_prompt [50,768]
    const float* pe = (const float*)d_in[1];   // patch_embeds [1024,197,768]
    float* out = (float*)d_out;

    cudaFuncSetAttribute(dist_kernel, cudaFuncAttributeMaxDynamicSharedMemorySize,
                         SMEM_BYTES);

    prep_kernel<<<MPAD, 256>>>(src);
    dist_kernel<<<NBLK, 256, SMEM_BYTES>>>(pe);
    finish_kernel<<<1, 1>>>(out);
}

// round 5
// speedup vs baseline: 4.6144x; 1.3022x over previous
#include <cuda_runtime.h>
#include <cuda_bf16.h>
#include <cstdint>

#define NPROMPT 50
#define MPAD 64              // padded prompt count (GEMM M)
#define D 768
#define KC 64                // k per chunk
#define NCHUNK (D / KC)      // 12
#define NTILE 128            // pe rows per CTA (GEMM N)
#define NVEC 201728          // 1024 * 197
#define NBLK (NVEC / NTILE)  // 1576 exactly
#define EPSV 1e-6f

#define LDA 72               // A-chunk smem row stride (halves): 144B, conflict-free ldsm
#define LDB 72               // B-chunk smem row stride (halves)

__device__ __align__(16) __nv_bfloat16 g_B[MPAD * D];
__device__ float g_ns[MPAD];
__device__ double g_acc;

// ---------------------------------------------------------------- prep ----
__global__ void prep_kernel(const float* __restrict__ src) {
    int p = blockIdx.x, tid = threadIdx.x;
    float local = 0.f;
    for (int k = tid; k < D; k += blockDim.x) {
        float v = (p < NPROMPT) ? src[p * D + k] + EPSV : 0.f;
        g_B[p * D + k] = __float2bfloat16(v);
        local += v * v;
    }
    __shared__ float sh[256];
    sh[tid] = local;
    __syncthreads();
    for (int s = 128; s > 0; s >>= 1) {
        if (tid < s) sh[tid] += sh[tid + s];
        __syncthreads();
    }
    if (tid == 0) {
        g_ns[p] = sh[0];
        if (p == 0) g_acc = 0.0;
    }
}

// ------------------------------------------------------------- helpers ----
__device__ __forceinline__ uint32_t pack_bf2(float lo, float hi) {
    __nv_bfloat162 t = __floats2bfloat162_rn(lo, hi);
    return *reinterpret_cast<uint32_t*>(&t);
}

__device__ __forceinline__ void ldsm4(uint32_t& r0, uint32_t& r1, uint32_t& r2,
                                      uint32_t& r3, uint32_t addr) {
    asm volatile("ldmatrix.sync.aligned.m8n8.x4.shared.b16 {%0,%1,%2,%3}, [%4];\n"
                 : "=r"(r0), "=r"(r1), "=r"(r2), "=r"(r3)
                 : "r"(addr));
}

__device__ __forceinline__ void mma16816(float* c, uint32_t a0, uint32_t a1,
                                         uint32_t a2, uint32_t a3, uint32_t b0,
                                         uint32_t b1) {
    asm volatile(
        "mma.sync.aligned.m16n8k16.row.col.f32.bf16.bf16.f32 "
        "{%0,%1,%2,%3}, {%4,%5,%6,%7}, {%8,%9}, {%0,%1,%2,%3};\n"
        : "+f"(c[0]), "+f"(c[1]), "+f"(c[2]), "+f"(c[3])
        : "r"(a0), "r"(a1), "r"(a2), "r"(a3), "r"(b0), "r"(b1));
}

// ---------------------------------------------------------------- main ----
// smem per CTA: A chunk double-buffer [2 x 64 x 72 halves] (18.4 KB)
//             + B chunk double-buffer [2 x 128 x 72 halves] (36.9 KB)
//             + sNpe[128] + sNs[64] + sRed[8]
constexpr int SA_HALVES = 2 * MPAD * LDA;
constexpr int SB_HALVES = 2 * NTILE * LDB;
constexpr int SMEM_BYTES = (SA_HALVES + SB_HALVES) * 2 + (NTILE + MPAD + 8) * 4;

__global__ void __launch_bounds__(256, 2)
dist_kernel(const float* __restrict__ pe) {
    extern __shared__ char smem_raw[];
    __nv_bfloat16* sA = (__nv_bfloat16*)smem_raw;
    __nv_bfloat16* sB = sA + SA_HALVES;
    float* sNpe = (float*)(sB + SB_HALVES);
    float* sNs = sNpe + NTILE;
    float* sRed = sNs + MPAD;

    const int tid = threadIdx.x;
    const int warp = tid >> 5, lane = tid & 31;
    const int m_base = (warp >> 1) * 16;  // 4 warps over M=64 prompts
    const int n_base = (warp & 1) * 64;   // 2 warps over N=128 pe rows

    if (tid < MPAD) sNs[tid] = g_ns[tid];

    // ---- loader mappings
    // B: thread owns pe row r0 = tid>>1, 32-float half c0
    const float* peBase = pe + (size_t)blockIdx.x * NTILE * D;
    const int r0 = tid >> 1;
    const int c0 = (tid & 1) * 32;
    const float* rowPtr = peBase + (size_t)r0 * D + c0;
    float nacc = 0.f;

    // A: 512 uint4 per chunk; thread loads 2 (rows ra0=tid>>2, q=(tid&3)*2..+1)
    const int ra = tid >> 2;          // 0..63 prompt row
    const int qa = (tid & 3) * 2;     // uint4 index within 8 per row

    float4 v[8];
    uint4 au[2];

#define LDGS_B(ck)                                                            \
    {                                                                         \
        const float* p = rowPtr + (ck)*KC;                                    \
        _Pragma("unroll") for (int j = 0; j < 8; ++j)                         \
            v[j] = *(const float4*)(p + j * 4);                               \
    }
#define LDG_A(ck)                                                             \
    {                                                                         \
        const uint4* gs = (const uint4*)(g_B + ra * D + (ck)*KC);             \
        au[0] = gs[qa];                                                       \
        au[1] = gs[qa + 1];                                                   \
    }
#define STS_B(buf)                                                            \
    {                                                                         \
        __nv_bfloat16* dst = sB + (buf)*NTILE * LDB + r0 * LDB + c0;          \
        _Pragma("unroll") for (int j = 0; j < 8; ++j) {                       \
            nacc += v[j].x * v[j].x + v[j].y * v[j].y + v[j].z * v[j].z +     \
                    v[j].w * v[j].w;                                          \
            uint2 u;                                                          \
            u.x = pack_bf2(v[j].x, v[j].y);                                   \
            u.y = pack_bf2(v[j].z, v[j].w);                                   \
            *(uint2*)(dst + j * 4) = u;                                       \
        }                                                                     \
    }
#define STS_A(buf)                                                            \
    {                                                                         \
        __nv_bfloat16* dst = sA + (buf)*MPAD * LDA + ra * LDA + qa * 8;       \
        *(uint4*)dst = au[0];                                                 \
        *(uint4*)(dst + 8) = au[1];                                           \
    }

    // accumulators: warp tile M16 x N64 -> 8 n8 tiles
    float acc[8][4];
#pragma unroll
    for (int j = 0; j < 8; ++j)
#pragma unroll
        for (int q = 0; q < 4; ++q) acc[j][q] = 0.f;

    const uint32_t sA_u = (uint32_t)__cvta_generic_to_shared(sA);
    const uint32_t sB_u = (uint32_t)__cvta_generic_to_shared(sB);
    const uint32_t a_off =
        (uint32_t)((m_base + (lane & 15)) * LDA + (lane >> 4) * 8) * 2;
    const uint32_t b_row = (uint32_t)(n_base + ((lane >> 4) & 1) * 8 + (lane & 7));
    const uint32_t b_k = ((lane >> 3) & 1) * 8;

#define STEP(s, abase, bbase)                                                 \
    {                                                                         \
        uint32_t a0, a1, a2, a3;                                              \
        ldsm4(a0, a1, a2, a3, (abase) + a_off + (s)*16 * 2);                  \
        _Pragma("unroll") for (int jj = 0; jj < 4; ++jj) {                    \
            uint32_t b0, b1, b2, b3;                                          \
            uint32_t baddr =                                                  \
                (bbase) + ((b_row + jj * 16) * LDB + (s)*16 + b_k) * 2;       \
            ldsm4(b0, b1, b2, b3, baddr);                                     \
            mma16816(acc[2 * jj], a0, a1, a2, a3, b0, b1);                    \
            mma16816(acc[2 * jj + 1], a0, a1, a2, a3, b2, b3);                \
        }                                                                     \
    }

    // prologue: chunk 0 -> buffer 0
    LDGS_B(0);
    LDG_A(0);
    STS_B(0);
    STS_A(0);
    __syncthreads();

    for (int it = 0; it < NCHUNK; ++it) {
        const uint32_t abase = sA_u + (uint32_t)((it & 1) * MPAD * LDA * 2);
        const uint32_t bbase = sB_u + (uint32_t)((it & 1) * NTILE * LDB * 2);
        const bool dl = (it + 1) < NCHUNK;

        if (dl) { LDGS_B(it + 1); LDG_A(it + 1); }  // prefetch into regs
        STEP(0, abase, bbase);
        STEP(1, abase, bbase);
        STEP(2, abase, bbase);
        STEP(3, abase, bbase);
        if (dl) { STS_B((it + 1) & 1); STS_A((it + 1) & 1); }
        __syncthreads();
    }

    // ---- |pe|^2 per row: combine the two half-row partials
    nacc += __shfl_xor_sync(0xffffffffu, nacc, 1);
    if ((tid & 1) == 0) sNpe[r0] = nacc;
    __syncthreads();

    // ---- epilogue: d = sqrt(|s'|^2 + |pe|^2 - 2 dot), mask prompts >= 50
    float lsum = 0.f;
    const int r = lane >> 2, c2 = (lane & 3) * 2;
#pragma unroll
    for (int j = 0; j < 8; ++j) {
        int n = n_base + j * 8 + c2;   // pe row index
        float np0 = sNpe[n], np1 = sNpe[n + 1];
        int m0 = m_base + r;           // prompt index
        if (m0 < NPROMPT) {
            float ns0 = sNs[m0];
            lsum += sqrtf(fmaxf(ns0 + np0 - 2.f * acc[j][0], 0.f));
            lsum += sqrtf(fmaxf(ns0 + np1 - 2.f * acc[j][1], 0.f));
        }
        int m1 = m0 + 8;
        if (m1 < NPROMPT) {
            float ns1 = sNs[m1];
            lsum += sqrtf(fmaxf(ns1 + np0 - 2.f * acc[j][2], 0.f));
            lsum += sqrtf(fmaxf(ns1 + np1 - 2.f * acc[j][3], 0.f));
        }
    }
#pragma unroll
    for (int o = 16; o > 0; o >>= 1)
        lsum += __shfl_xor_sync(0xffffffffu, lsum, o);
    if (lane == 0) sRed[warp] = lsum;
    __syncthreads();
    if (warp == 0) {
        float s = (lane < 8) ? sRed[lane] : 0.f;
#pragma unroll
        for (int o = 4; o > 0; o >>= 1)
            s += __shfl_xor_sync(0xffffffffu, s, o);
        if (lane == 0) atomicAdd(&g_acc, (double)s);
    }
}

// -------------------------------------------------------------- finish ----
__global__ void finish_kernel(float* out) {
    out[0] = (float)(g_acc * (1.0 / ((double)NPROMPT * 197.0 * 1024.0)));
}

// -------------------------------------------------------------- launch ----
extern "C" void kernel_launch(void* const* d_in, const int* in_sizes, int n_in,
                              void* d_out, int out_size) {
    const float* src = (const float*)d_in[0];  // source_prompt [50,768]
    const float* pe = (const float*)d_in[1];   // patch_embeds [1024,197,768]
    float* out = (float*)d_out;

    cudaFuncSetAttribute(dist_kernel, cudaFuncAttributeMaxDynamicSharedMemorySize,
                         SMEM_BYTES);

    prep_kernel<<<MPAD, 256>>>(src);
    dist_kernel<<<NBLK, 256, SMEM_BYTES>>>(pe);
    finish_kernel<<<1, 1>>>(out);
}

// round 7
// speedup vs baseline: 4.8400x; 1.0489x over previous
#include <cuda_runtime.h>
#include <cuda_bf16.h>
#include <cstdint>

#define NPROMPT 50
#define MPAD 64              // padded prompt count (GEMM M)
#define D 768
#define KC 64                // k per chunk
#define NCHUNK (D / KC)      // 12
#define NTILE 128            // pe rows per CTA (GEMM N)
#define NVEC 201728          // 1024 * 197
#define NBLK (NVEC / NTILE)  // 1576 exactly
#define EPSV 1e-6f

#define LDA 72               // A-chunk smem row stride (halves): 144B
#define LDB 72               // B-chunk smem row stride (halves)

__device__ __align__(16) __nv_bfloat16 g_B[MPAD * D];
__device__ float g_ns[MPAD];
__device__ double g_acc;

// ---------------------------------------------------------------- prep ----
__global__ void prep_kernel(const float* __restrict__ src) {
    int p = blockIdx.x, tid = threadIdx.x;
    float local = 0.f;
    for (int k = tid; k < D; k += blockDim.x) {
        float v = (p < NPROMPT) ? src[p * D + k] + EPSV : 0.f;
        g_B[p * D + k] = __float2bfloat16(v);
        local += v * v;
    }
    __shared__ float sh[256];
    sh[tid] = local;
    __syncthreads();
    for (int s = 128; s > 0; s >>= 1) {
        if (tid < s) sh[tid] += sh[tid + s];
        __syncthreads();
    }
    if (tid == 0) {
        g_ns[p] = sh[0];
        if (p == 0) g_acc = 0.0;
    }
}

// ------------------------------------------------------------- helpers ----
__device__ __forceinline__ uint32_t pack_bf2(float lo, float hi) {
    __nv_bfloat162 t = __floats2bfloat162_rn(lo, hi);
    return *reinterpret_cast<uint32_t*>(&t);
}

__device__ __forceinline__ void ldsm4(uint32_t& r0, uint32_t& r1, uint32_t& r2,
                                      uint32_t& r3, uint32_t addr) {
    asm volatile("ldmatrix.sync.aligned.m8n8.x4.shared.b16 {%0,%1,%2,%3}, [%4];\n"
                 : "=r"(r0), "=r"(r1), "=r"(r2), "=r"(r3)
                 : "r"(addr));
}

__device__ __forceinline__ void mma16816(float* c, uint32_t a0, uint32_t a1,
                                         uint32_t a2, uint32_t a3, uint32_t b0,
                                         uint32_t b1) {
    asm volatile(
        "mma.sync.aligned.m16n8k16.row.col.f32.bf16.bf16.f32 "
        "{%0,%1,%2,%3}, {%4,%5,%6,%7}, {%8,%9}, {%0,%1,%2,%3};\n"
        : "+f"(c[0]), "+f"(c[1]), "+f"(c[2]), "+f"(c[3])
        : "r"(a0), "r"(a1), "r"(a2), "r"(a3), "r"(b0), "r"(b1));
}

__device__ __forceinline__ void cp_async16(uint32_t dst, const void* src) {
    asm volatile("cp.async.cg.shared.global [%0], [%1], 16;" ::"r"(dst),
                 "l"(src)
                 : "memory");
}
#define CP_COMMIT() asm volatile("cp.async.commit_group;" ::: "memory")
#define CP_WAIT0() asm volatile("cp.async.wait_group 0;" ::: "memory")

// ---------------------------------------------------------------- main ----
// smem per CTA: A db [2 x 64 x 72 halves] + B db [2 x 128 x 72 halves]
//             + sNpe[128] + sNs[64] + sRed[8]   -> 56.1 KB, 3 CTAs/SM
constexpr int SA_HALVES = 2 * MPAD * LDA;
constexpr int SB_HALVES = 2 * NTILE * LDB;
constexpr int SMEM_BYTES = (SA_HALVES + SB_HALVES) * 2 + (NTILE + MPAD + 8) * 4;

__global__ void __launch_bounds__(256, 3)
dist_kernel(const float* __restrict__ pe) {
    extern __shared__ char smem_raw[];
    __nv_bfloat16* sA = (__nv_bfloat16*)smem_raw;
    __nv_bfloat16* sB = sA + SA_HALVES;
    float* sNpe = (float*)(sB + SB_HALVES);
    float* sNs = sNpe + NTILE;
    float* sRed = sNs + MPAD;

    const int tid = threadIdx.x;
    const int warp = tid >> 5, lane = tid & 31;
    const int m_base = (warp >> 1) * 16;  // 4 warps over M=64 prompts
    const int n_base = (warp & 1) * 64;   // 2 warps over N=128 pe rows

    if (tid < MPAD) sNs[tid] = g_ns[tid];

    // ---- loader mappings
    // B: thread owns pe row r0 = tid>>1, 32-float half c0; two 16-float quarters
    const float* peBase = pe + (size_t)blockIdx.x * NTILE * D;
    const int r0 = tid >> 1;
    const int c0 = (tid & 1) * 32;
    const float* rowPtr = peBase + (size_t)r0 * D + c0;
    float nacc = 0.f;

    // A (cp.async): thread copies 2 consecutive 16B slots; row ra, slots qa, qa+1
    const int ra = tid >> 2;
    const int qa = (tid & 3) * 2;
    const uint32_t sA_u = (uint32_t)__cvta_generic_to_shared(sA);
    const uint32_t sB_u = (uint32_t)__cvta_generic_to_shared(sB);
    const uint32_t aDst = sA_u + (uint32_t)(ra * LDA + qa * 8) * 2;
    const __nv_bfloat16* aSrc = g_B + ra * D + qa * 8;

    float4 v[4];

#define CPA_A(ck, buf)                                                        \
    {                                                                         \
        uint32_t d = aDst + (uint32_t)((buf)*MPAD * LDA * 2);                 \
        const __nv_bfloat16* s = aSrc + (ck)*KC;                              \
        cp_async16(d, s);                                                     \
        cp_async16(d + 16, s + 8); /* +16 BYTES dst, +8 HALVES src = slot qa+1 */ \
        CP_COMMIT();                                                          \
    }
#define LDG_B(ck, h)                                                          \
    {                                                                         \
        const float* p = rowPtr + (ck)*KC + (h)*16;                           \
        _Pragma("unroll") for (int j = 0; j < 4; ++j)                         \
            v[j] = *(const float4*)(p + j * 4);                               \
    }
#define STS_B(buf, h)                                                         \
    {                                                                         \
        __nv_bfloat16* dst = sB + (buf)*NTILE * LDB + r0 * LDB + c0 + (h)*16; \
        _Pragma("unroll") for (int j = 0; j < 4; ++j) {                       \
            nacc += v[j].x * v[j].x + v[j].y * v[j].y + v[j].z * v[j].z +     \
                    v[j].w * v[j].w;                                          \
            uint2 u;                                                          \
            u.x = pack_bf2(v[j].x, v[j].y);                                   \
            u.y = pack_bf2(v[j].z, v[j].w);                                   \
            *(uint2*)(dst + j * 4) = u;                                       \
        }                                                                     \
    }

    // accumulators: warp tile M16 x N64 -> 8 n8 tiles
    float acc[8][4];
#pragma unroll
    for (int j = 0; j < 8; ++j)
#pragma unroll
        for (int q = 0; q < 4; ++q) acc[j][q] = 0.f;

    const uint32_t a_off =
        (uint32_t)((m_base + (lane & 15)) * LDA + (lane >> 4) * 8) * 2;
    const uint32_t b_row = (uint32_t)(n_base + ((lane >> 4) & 1) * 8 + (lane & 7));
    const uint32_t b_k = ((lane >> 3) & 1) * 8;

#define STEP(s, abase, bbase)                                                 \
    {                                                                         \
        uint32_t a0, a1, a2, a3;                                              \
        ldsm4(a0, a1, a2, a3, (abase) + a_off + (s)*16 * 2);                  \
        _Pragma("unroll") for (int jj = 0; jj < 4; ++jj) {                    \
            uint32_t b0, b1, b2, b3;                                          \
            uint32_t baddr =                                                  \
                (bbase) + ((b_row + jj * 16) * LDB + (s)*16 + b_k) * 2;       \
            ldsm4(b0, b1, b2, b3, baddr);                                     \
            mma16816(acc[2 * jj], a0, a1, a2, a3, b0, b1);                    \
            mma16816(acc[2 * jj + 1], a0, a1, a2, a3, b2, b3);                \
        }                                                                     \
    }

    // prologue: chunk 0 -> buffer 0
    CPA_A(0, 0);
    LDG_B(0, 0);
    STS_B(0, 0);
    LDG_B(0, 1);
    STS_B(0, 1);
    CP_WAIT0();
    __syncthreads();

    for (int it = 0; it < NCHUNK; ++it) {
        const uint32_t abase = sA_u + (uint32_t)((it & 1) * MPAD * LDA * 2);
        const uint32_t bbase = sB_u + (uint32_t)((it & 1) * NTILE * LDB * 2);
        const bool dl = (it + 1) < NCHUNK;
        const int nb = (it + 1) & 1;

        if (dl) { CPA_A(it + 1, nb); LDG_B(it + 1, 0); }
        STEP(0, abase, bbase);
        STEP(1, abase, bbase);
        if (dl) { STS_B(nb, 0); LDG_B(it + 1, 1); }
        STEP(2, abase, bbase);
        STEP(3, abase, bbase);
        if (dl) { STS_B(nb, 1); CP_WAIT0(); }
        __syncthreads();
    }

    // ---- |pe|^2 per row: combine the two half-row partials
    nacc += __shfl_xor_sync(0xffffffffu, nacc, 1);
    if ((tid & 1) == 0) sNpe[r0] = nacc;
    __syncthreads();

    // ---- epilogue: d = sqrt(|s'|^2 + |pe|^2 - 2 dot), mask prompts >= 50
    float lsum = 0.f;
    const int r = lane >> 2, c2 = (lane & 3) * 2;
#pragma unroll
    for (int j = 0; j < 8; ++j) {
        int n = n_base + j * 8 + c2;   // pe row index
        float np0 = sNpe[n], np1 = sNpe[n + 1];
        int m0 = m_base + r;           // prompt index
        if (m0 < NPROMPT) {
            float ns0 = sNs[m0];
            lsum += sqrtf(fmaxf(ns0 + np0 - 2.f * acc[j][0], 0.f));
            lsum += sqrtf(fmaxf(ns0 + np1 - 2.f * acc[j][1], 0.f));
        }
        int m1 = m0 + 8;
        if (m1 < NPROMPT) {
            float ns1 = sNs[m1];
            lsum += sqrtf(fmaxf(ns1 + np0 - 2.f * acc[j][2], 0.f));
            lsum += sqrtf(fmaxf(ns1 + np1 - 2.f * acc[j][3], 0.f));
        }
    }
#pragma unroll
    for (int o = 16; o > 0; o >>= 1)
        lsum += __shfl_xor_sync(0xffffffffu, lsum, o);
    if (lane == 0) sRed[warp] = lsum;
    __syncthreads();
    if (warp == 0) {
        float s = (lane < 8) ? sRed[lane] : 0.f;
#pragma unroll
        for (int o = 4; o > 0; o >>= 1)
            s += __shfl_xor_sync(0xffffffffu, s, o);
        if (lane == 0) atomicAdd(&g_acc, (double)s);
    }
}

// -------------------------------------------------------------- finish ----
__global__ void finish_kernel(float* out) {
    out[0] = (float)(g_acc * (1.0 / ((double)NPROMPT * 197.0 * 1024.0)));
}

// -------------------------------------------------------------- launch ----
extern "C" void kernel_launch(void* const* d_in, const int* in_sizes, int n_in,
                              void* d_out, int out_size) {
    const float* src = (const float*)d_in[0];  // source_prompt [50,768]
    const float* pe = (const float*)d_in[1];   // patch_embeds [1024,197,768]
    float* out = (float*)d_out;

    cudaFuncSetAttribute(dist_kernel, cudaFuncAttributeMaxDynamicSharedMemorySize,
                         SMEM_BYTES);

    prep_kernel<<<MPAD, 256>>>(src);
    dist_kernel<<<NBLK, 256, SMEM_BYTES>>>(pe);
    finish_kernel<<<1, 1>>>(out);
}

// round 8
// speedup vs baseline: 6.5288x; 1.3489x over previous
#include <cuda_runtime.h>
#include <cuda_bf16.h>
#include <cstdint>

#define NPROMPT 50
#define MPAD 64              // padded prompt count (GEMM M)
#define D 768
#define KC 64                // k per chunk
#define NCHUNK (D / KC)      // 12
#define NTILE 128            // pe rows per CTA (GEMM N)
#define NVEC 201728          // 1024 * 197
#define NBLK (NVEC / NTILE)  // 1576 exactly
#define EPSV 1e-6f
#define NTHREADS 512

#define LDA 72               // A-chunk smem row stride (halves): 144B
#define LDB 72               // B-chunk smem row stride (halves)

__device__ __align__(16) __nv_bfloat16 g_B[MPAD * D];
__device__ float g_ns[MPAD];
__device__ double g_acc;

// ---------------------------------------------------------------- prep ----
__global__ void prep_kernel(const float* __restrict__ src) {
    int p = blockIdx.x, tid = threadIdx.x;
    float local = 0.f;
    for (int k = tid; k < D; k += blockDim.x) {
        float v = (p < NPROMPT) ? src[p * D + k] + EPSV : 0.f;
        g_B[p * D + k] = __float2bfloat16(v);
        local += v * v;
    }
    __shared__ float sh[256];
    sh[tid] = local;
    __syncthreads();
    for (int s = 128; s > 0; s >>= 1) {
        if (tid < s) sh[tid] += sh[tid + s];
        __syncthreads();
    }
    if (tid == 0) {
        g_ns[p] = sh[0];
        if (p == 0) g_acc = 0.0;
    }
}

// ------------------------------------------------------------- helpers ----
__device__ __forceinline__ uint32_t pack_bf2(float lo, float hi) {
    __nv_bfloat162 t = __floats2bfloat162_rn(lo, hi);
    return *reinterpret_cast<uint32_t*>(&t);
}

__device__ __forceinline__ void ldsm4(uint32_t& r0, uint32_t& r1, uint32_t& r2,
                                      uint32_t& r3, uint32_t addr) {
    asm volatile("ldmatrix.sync.aligned.m8n8.x4.shared.b16 {%0,%1,%2,%3}, [%4];\n"
                 : "=r"(r0), "=r"(r1), "=r"(r2), "=r"(r3)
                 : "r"(addr));
}

__device__ __forceinline__ void mma16816(float* c, uint32_t a0, uint32_t a1,
                                         uint32_t a2, uint32_t a3, uint32_t b0,
                                         uint32_t b1) {
    asm volatile(
        "mma.sync.aligned.m16n8k16.row.col.f32.bf16.bf16.f32 "
        "{%0,%1,%2,%3}, {%4,%5,%6,%7}, {%8,%9}, {%0,%1,%2,%3};\n"
        : "+f"(c[0]), "+f"(c[1]), "+f"(c[2]), "+f"(c[3])
        : "r"(a0), "r"(a1), "r"(a2), "r"(a3), "r"(b0), "r"(b1));
}

__device__ __forceinline__ void cp_async16(uint32_t dst, const void* src) {
    asm volatile("cp.async.cg.shared.global [%0], [%1], 16;" ::"r"(dst),
                 "l"(src)
                 : "memory");
}
#define CP_COMMIT() asm volatile("cp.async.commit_group;" ::: "memory")
#define CP_WAIT0() asm volatile("cp.async.wait_group 0;" ::: "memory")

// ---------------------------------------------------------------- main ----
// smem per CTA: A db [2 x 64 x 72 halves] + B db [2 x 128 x 72 halves]
//             + sNpe[128] + sNs[64] + sRed[16]  -> ~56.2 KB, 2 CTAs/SM
constexpr int SA_HALVES = 2 * MPAD * LDA;
constexpr int SB_HALVES = 2 * NTILE * LDB;
constexpr int SMEM_BYTES = (SA_HALVES + SB_HALVES) * 2 + (NTILE + MPAD + 16) * 4;

__global__ void __launch_bounds__(NTHREADS, 2)
dist_kernel(const float* __restrict__ pe) {
    extern __shared__ char smem_raw[];
    __nv_bfloat16* sA = (__nv_bfloat16*)smem_raw;
    __nv_bfloat16* sB = sA + SA_HALVES;
    float* sNpe = (float*)(sB + SB_HALVES);
    float* sNs = sNpe + NTILE;
    float* sRed = sNs + MPAD;

    const int tid = threadIdx.x;
    const int warp = tid >> 5, lane = tid & 31;
    const int m_base = (warp >> 2) * 16;  // 4 m-groups over M=64 prompts
    const int n_base = (warp & 3) * 32;   // 4 n-groups over N=128 pe rows

    if (tid < MPAD) sNs[tid] = g_ns[tid];

    // ---- loader mappings
    // B: 4 threads per pe row; thread owns 16-float quarter c0 of row r0
    const float* peBase = pe + (size_t)blockIdx.x * NTILE * D;
    const int r0 = tid >> 2;           // 0..127
    const int c0 = (tid & 3) * 16;     // float offset within 64-chunk
    const float* rowPtr = peBase + (size_t)r0 * D + c0;
    float nacc = 0.f;

    // A (cp.async): 8 threads per prompt row; thread copies 1 x 16B slot
    const int ra = tid >> 3;           // 0..63
    const int qa = tid & 7;            // 16B slot within row
    const uint32_t sA_u = (uint32_t)__cvta_generic_to_shared(sA);
    const uint32_t sB_u = (uint32_t)__cvta_generic_to_shared(sB);
    const uint32_t aDst = sA_u + (uint32_t)(ra * LDA + qa * 8) * 2;
    const __nv_bfloat16* aSrc = g_B + ra * D + qa * 8;

    float4 v[4];

#define CPA_A(ck, buf)                                                        \
    {                                                                         \
        cp_async16(aDst + (uint32_t)((buf)*MPAD * LDA * 2),                   \
                   aSrc + (ck)*KC);                                           \
        CP_COMMIT();                                                          \
    }
#define LDG_B(ck)                                                             \
    {                                                                         \
        const float* p = rowPtr + (ck)*KC;                                    \
        _Pragma("unroll") for (int j = 0; j < 4; ++j)                         \
            v[j] = *(const float4*)(p + j * 4);                               \
    }
#define STS_B(buf)                                                            \
    {                                                                         \
        __nv_bfloat16* dst = sB + (buf)*NTILE * LDB + r0 * LDB + c0;          \
        _Pragma("unroll") for (int j = 0; j < 4; ++j) {                       \
            nacc += v[j].x * v[j].x + v[j].y * v[j].y + v[j].z * v[j].z +     \
                    v[j].w * v[j].w;                                          \
            uint2 u;                                                          \
            u.x = pack_bf2(v[j].x, v[j].y);                                   \
            u.y = pack_bf2(v[j].z, v[j].w);                                   \
            *(uint2*)(dst + j * 4) = u;                                       \
        }                                                                     \
    }

    // accumulators: warp tile M16 x N32 -> 4 n8 tiles
    float acc[4][4];
#pragma unroll
    for (int j = 0; j < 4; ++j)
#pragma unroll
        for (int q = 0; q < 4; ++q) acc[j][q] = 0.f;

    const uint32_t a_off =
        (uint32_t)((m_base + (lane & 15)) * LDA + (lane >> 4) * 8) * 2;
    const uint32_t b_row = (uint32_t)(n_base + ((lane >> 4) & 1) * 8 + (lane & 7));
    const uint32_t b_k = ((lane >> 3) & 1) * 8;

#define STEP(s, abase, bbase)                                                 \
    {                                                                         \
        uint32_t a0, a1, a2, a3;                                              \
        ldsm4(a0, a1, a2, a3, (abase) + a_off + (s)*16 * 2);                  \
        _Pragma("unroll") for (int jj = 0; jj < 2; ++jj) {                    \
            uint32_t b0, b1, b2, b3;                                          \
            uint32_t baddr =                                                  \
                (bbase) + ((b_row + jj * 16) * LDB + (s)*16 + b_k) * 2;       \
            ldsm4(b0, b1, b2, b3, baddr);                                     \
            mma16816(acc[2 * jj], a0, a1, a2, a3, b0, b1);                    \
            mma16816(acc[2 * jj + 1], a0, a1, a2, a3, b2, b3);                \
        }                                                                     \
    }

    // prologue: chunk 0 -> buffer 0
    CPA_A(0, 0);
    LDG_B(0);
    STS_B(0);
    CP_WAIT0();
    __syncthreads();

    for (int it = 0; it < NCHUNK; ++it) {
        const uint32_t abase = sA_u + (uint32_t)((it & 1) * MPAD * LDA * 2);
        const uint32_t bbase = sB_u + (uint32_t)((it & 1) * NTILE * LDB * 2);
        const bool dl = (it + 1) < NCHUNK;
        const int nb = (it + 1) & 1;

        if (dl) { LDG_B(it + 1); CPA_A(it + 1, nb); }  // full-chunk prefetch
        STEP(0, abase, bbase);
        STEP(1, abase, bbase);
        STEP(2, abase, bbase);
        STEP(3, abase, bbase);
        if (dl) { STS_B(nb); CP_WAIT0(); }
        __syncthreads();
    }

    // ---- |pe|^2 per row: combine the four quarter-row partials
    nacc += __shfl_xor_sync(0xffffffffu, nacc, 1);
    nacc += __shfl_xor_sync(0xffffffffu, nacc, 2);
    if ((tid & 3) == 0) sNpe[r0] = nacc;
    __syncthreads();

    // ---- epilogue: d = sqrt(|s'|^2 + |pe|^2 - 2 dot), mask prompts >= 50
    float lsum = 0.f;
    const int r = lane >> 2, c2 = (lane & 3) * 2;
#pragma unroll
    for (int j = 0; j < 4; ++j) {
        int n = n_base + j * 8 + c2;   // pe row index
        float np0 = sNpe[n], np1 = sNpe[n + 1];
        int m0 = m_base + r;           // prompt index
        if (m0 < NPROMPT) {
            float ns0 = sNs[m0];
            lsum += sqrtf(fmaxf(ns0 + np0 - 2.f * acc[j][0], 0.f));
            lsum += sqrtf(fmaxf(ns0 + np1 - 2.f * acc[j][1], 0.f));
        }
        int m1 = m0 + 8;
        if (m1 < NPROMPT) {
            float ns1 = sNs[m1];
            lsum += sqrtf(fmaxf(ns1 + np0 - 2.f * acc[j][2], 0.f));
            lsum += sqrtf(fmaxf(ns1 + np1 - 2.f * acc[j][3], 0.f));
        }
    }
#pragma unroll
    for (int o = 16; o > 0; o >>= 1)
        lsum += __shfl_xor_sync(0xffffffffu, lsum, o);
    if (lane == 0) sRed[warp] = lsum;
    __syncthreads();
    if (warp == 0) {
        float s = (lane < 16) ? sRed[lane] : 0.f;
#pragma unroll
        for (int o = 8; o > 0; o >>= 1)
            s += __shfl_xor_sync(0xffffffffu, s, o);
        if (lane == 0) atomicAdd(&g_acc, (double)s);
    }
}

// -------------------------------------------------------------- finish ----
__global__ void finish_kernel(float* out) {
    out[0] = (float)(g_acc * (1.0 / ((double)NPROMPT * 197.0 * 1024.0)));
}

// -------------------------------------------------------------- launch ----
extern "C" void kernel_launch(void* const* d_in, const int* in_sizes, int n_in,
                              void* d_out, int out_size) {
    const float* src = (const float*)d_in[0];  // source_prompt [50,768]
    const float* pe = (const float*)d_in[1];   // patch_embeds [1024,197,768]
    float* out = (float*)d_out;

    cudaFuncSetAttribute(dist_kernel, cudaFuncAttributeMaxDynamicSharedMemorySize,
                         SMEM_BYTES);

    prep_kernel<<<MPAD, 256>>>(src);
    dist_kernel<<<NBLK, NTHREADS, SMEM_BYTES>>>(pe);
    finish_kernel<<<1, 1>>>(out);
}